// round 5
// baseline (speedup 1.0000x reference)
#include <cuda_runtime.h>
#include <cstdint>

// ImageWarpingLayer: out = bilinear_sample(image, grid + flow)
// image: [B=16, H=512, W=512, C=8] f32   flow: [B, H, W, 2] f32 (dy, dx)
// TF dense_image_warp semantics: floor clamped to [0, size-2],
// alpha = clip(q - floor, 0, 1).
//
// Work-unit = (pixel, float2-quarter-of-C): 4 threads per pixel, LDG.64
// gathers. Each warp-level gather instruction spans only ~256B (8 pixels),
// minimizing within-instruction L1tex replays (2.07 cyc/wf) in favor of
// cross-instruction wavefronts (1.0 cyc/wf). Output staged in SMEM and
// written with one 4KB cp.async.bulk (TMA) per block - no store wavefronts.

#define Bn 16
#define Hn 512
#define Wn 512
#define Cn 8

#define UNITS_PER_BLOCK 512                  // 2 units/thread * 256 threads
#define TOTAL_UNITS (Bn * Hn * Wn * 4)       // 16777216 (4 units per pixel)

__device__ __forceinline__ uint32_t smem_u32(const void* p) {
    uint32_t a;
    asm("{ .reg .u64 t; cvta.to.shared.u64 t, %1; cvt.u32.u64 %0, t; }"
        : "=r"(a) : "l"(p));
    return a;
}

__global__ __launch_bounds__(256)
void warp_kernel(const float* __restrict__ image,
                 const float* __restrict__ flow,
                 float* __restrict__ out)
{
    __shared__ __align__(16) float2 buf[UNITS_PER_BLOCK];  // 4 KB

    const int base = blockIdx.x * UNITS_PER_BLOCK;
    const int t    = threadIdx.x;

#pragma unroll
    for (int k = 0; k < 2; k++) {
        const int slot = t + k * 256;
        const int uid  = base + slot;

        const int pix     = uid >> 2;        // pixel id
        const int quarter = uid & 3;         // which float2 of the 8 channels

        const int x = pix & (Wn - 1);
        const int y = (pix >> 9) & (Hn - 1);
        const int b = pix >> 18;

        // 4 lanes per pixel read the same float2 -> duplicates coalesce
        const float2 f = __ldg(reinterpret_cast<const float2*>(flow) + pix);
        const float qy = (float)y + f.x;
        const float qx = (float)x + f.y;

        const float fy = fminf(fmaxf(floorf(qy), 0.0f), (float)(Hn - 2));
        const float fx = fminf(fmaxf(floorf(qx), 0.0f), (float)(Wn - 2));
        const float ay = fminf(fmaxf(qy - fy, 0.0f), 1.0f);
        const float ax = fminf(fmaxf(qx - fx, 0.0f), 1.0f);

        const int iy = (int)fy;
        const int ix = (int)fx;

        // image[b, iy, ix, quarter*2]; tr = +C floats, bottom = +W*C floats
        const long top = (((long)b * Hn + iy) * Wn + ix) * Cn + quarter * 2;
        const long bot = top + (long)Wn * Cn;

        const float2 tl = __ldg(reinterpret_cast<const float2*>(image + top));
        const float2 tr = __ldg(reinterpret_cast<const float2*>(image + top + Cn));
        const float2 bl = __ldg(reinterpret_cast<const float2*>(image + bot));
        const float2 br = __ldg(reinterpret_cast<const float2*>(image + bot + Cn));

        float2 o;
        float tt, bo;
        tt  = fmaf(ax, tr.x - tl.x, tl.x);
        bo  = fmaf(ax, br.x - bl.x, bl.x);
        o.x = fmaf(ay, bo - tt, tt);
        tt  = fmaf(ax, tr.y - tl.y, tl.y);
        bo  = fmaf(ax, br.y - bl.y, bl.y);
        o.y = fmaf(ay, bo - tt, tt);

        buf[slot] = o;  // STS.64, conflict-free
    }

    __syncthreads();

    if (t == 0) {
        // Order generic-proxy smem writes before async-proxy read
        asm volatile("fence.proxy.async.shared::cta;" ::: "memory");
        const uint32_t s = smem_u32(buf);
        float* g = out + (long)base * 2;  // 2 floats per unit
        asm volatile(
            "cp.async.bulk.global.shared::cta.bulk_group [%0], [%1], %2;"
            :: "l"(g), "r"(s), "n"(UNITS_PER_BLOCK * 8) : "memory");
        asm volatile("cp.async.bulk.commit_group;" ::: "memory");
        asm volatile("cp.async.bulk.wait_group 0;" ::: "memory");
    }
}

extern "C" void kernel_launch(void* const* d_in, const int* in_sizes, int n_in,
                              void* d_out, int out_size)
{
    const float* image = (const float*)d_in[0];
    const float* flow  = (const float*)d_in[1];
    float* out = (float*)d_out;

    const int blocks = TOTAL_UNITS / UNITS_PER_BLOCK; // 32768
    warp_kernel<<<blocks, 256>>>(image, flow, out);
}